// round 1
// baseline (speedup 1.0000x reference)
#include <cuda_runtime.h>
#include <math.h>

#define NTOK   16384
#define EDIM   64
#define NH     8
#define HE     512
#define QKVDIM 1536
#define NITER  32

// Scratch (static device memory — allocation-free)
__device__ float g_qkv[NTOK * QKVDIM];   // per token: q[0:512) (pre-scaled), k[512:1024), v[1024:1536)
__device__ float g_res[NTOK * HE];       // per token: res[h*64+i]

// ---------------------------------------------------------------------------
// K1: fused QKV projection.  y[n,o] = sum_k x[n,k]*W[o,k] + b[o]
// q region additionally scaled by (alpha-1)/sqrt(e) so dot accumulation
// directly produces Xa for the bisection.
// Tile: M=64 tokens, N=128 outputs, K=64 (full).
// ---------------------------------------------------------------------------
__global__ __launch_bounds__(256) void k_qkv(
    const float* __restrict__ x,
    const float* __restrict__ Wq, const float* __restrict__ bq,
    const float* __restrict__ Wk, const float* __restrict__ bk,
    const float* __restrict__ Wv, const float* __restrict__ bv,
    const float* __restrict__ alpha_p)
{
    __shared__ float aT[64][64];    // aT[k][m]
    __shared__ float bT[64][128];   // bT[k][o]
    const int tid   = threadIdx.x;
    const int bm    = blockIdx.x;           // 0..255 (token tiles)
    const int oBase = blockIdx.y * 128;     // 0..1408 step 128

    // ---- load A tile (64 rows x 64 k), store transposed ----
    {
        int f = tid;
        #pragma unroll
        for (int rep = 0; rep < 4; rep++, f += 256) {
            int row = f >> 4;
            int c4  = f & 15;
            float4 v = *(const float4*)(x + (size_t)(bm * 64 + row) * 64 + c4 * 4);
            aT[c4 * 4 + 0][row] = v.x;
            aT[c4 * 4 + 1][row] = v.y;
            aT[c4 * 4 + 2][row] = v.z;
            aT[c4 * 4 + 3][row] = v.w;
        }
    }
    // ---- select weight matrix for this N-tile (no straddle: 512%128==0) ----
    const float* W; const float* bias;
    if (oBase < 512)       { W = Wq; bias = bq; }
    else if (oBase < 1024) { W = Wk; bias = bk; }
    else                   { W = Wv; bias = bv; }
    const int wBase = oBase & 511;

    // ---- load B tile (128 o x 64 k), store transposed ----
    {
        int f = tid;
        #pragma unroll
        for (int rep = 0; rep < 8; rep++, f += 256) {
            int o  = f >> 4;
            int c4 = f & 15;
            float4 v = *(const float4*)(W + (size_t)(wBase + o) * 64 + c4 * 4);
            bT[c4 * 4 + 0][o] = v.x;
            bT[c4 * 4 + 1][o] = v.y;
            bT[c4 * 4 + 2][o] = v.z;
            bT[c4 * 4 + 3][o] = v.w;
        }
    }
    __syncthreads();

    const int r0 = (tid >> 4) * 4;
    const int c0 = (tid & 15) * 8;
    float acc[4][8];
    #pragma unroll
    for (int r = 0; r < 4; r++)
        #pragma unroll
        for (int c = 0; c < 8; c++) acc[r][c] = 0.f;

    #pragma unroll 8
    for (int k = 0; k < 64; k++) {
        float4 a4  = *(const float4*)&aT[k][r0];
        float4 b4a = *(const float4*)&bT[k][c0];
        float4 b4b = *(const float4*)&bT[k][c0 + 4];
        float a[4] = {a4.x, a4.y, a4.z, a4.w};
        float b[8] = {b4a.x, b4a.y, b4a.z, b4a.w, b4b.x, b4b.y, b4b.z, b4b.w};
        #pragma unroll
        for (int r = 0; r < 4; r++)
            #pragma unroll
            for (int c = 0; c < 8; c++)
                acc[r][c] = fmaf(a[r], b[c], acc[r][c]);
    }

    const float am1   = alpha_p[0] - 1.f;
    const float scale = (oBase < 512) ? am1 * 0.125f : 1.f;   // 1/sqrt(64)=0.125

    float bb[8];
    #pragma unroll
    for (int c = 0; c < 8; c++) bb[c] = bias[wBase + c0 + c];

    #pragma unroll
    for (int r = 0; r < 4; r++) {
        float o0 = (acc[r][0] + bb[0]) * scale;
        float o1 = (acc[r][1] + bb[1]) * scale;
        float o2 = (acc[r][2] + bb[2]) * scale;
        float o3 = (acc[r][3] + bb[3]) * scale;
        float o4 = (acc[r][4] + bb[4]) * scale;
        float o5 = (acc[r][5] + bb[5]) * scale;
        float o6 = (acc[r][6] + bb[6]) * scale;
        float o7 = (acc[r][7] + bb[7]) * scale;
        float* dst = g_qkv + (size_t)(bm * 64 + r0 + r) * QKVDIM + oBase + c0;
        *(float4*)(dst)     = make_float4(o0, o1, o2, o3);
        *(float4*)(dst + 4) = make_float4(o4, o5, o6, o7);
    }
}

// ---------------------------------------------------------------------------
// K2: per-token attention scores + entmax bisection + att@V^T.
// 4 tokens per CTA, 64 threads per token, one score row per thread in regs.
// ---------------------------------------------------------------------------
__global__ __launch_bounds__(256) void k_attn(const float* __restrict__ alpha_p)
{
    __shared__ float kv[4][1024];   // per local token: k[0:512), v[512:1024)
    const int tid   = threadIdx.x;
    const int tok0  = blockIdx.x * 4;
    const int lt    = tid >> 6;       // local token
    const int i     = tid & 63;       // score row
    const int token = tok0 + lt;

    // cooperative load of k,v for 4 tokens (1024 float4)
    {
        int f = tid;
        #pragma unroll
        for (int rep = 0; rep < 4; rep++, f += 256) {
            int t    = f >> 8;
            int idx4 = f & 255;
            float4 v = *(const float4*)(g_qkv + (size_t)(tok0 + t) * QKVDIM + 512 + idx4 * 4);
            *(float4*)(&kv[t][idx4 * 4]) = v;
        }
    }
    // per-thread q column (pre-scaled by am1/sqrt(e) in K1)
    float q[NH];
    #pragma unroll
    for (int h = 0; h < NH; h++)
        q[h] = g_qkv[(size_t)token * QKVDIM + h * 64 + i];
    __syncthreads();

    const float am1 = alpha_p[0] - 1.f;
    const float inv = 1.f / am1;
    const bool fast = fabsf(inv - 2.f) < 1e-4f;   // alpha == 1.5 -> p(z)=z^2

    // Xa row: xa[j] = sum_h q[h] * k[h][j]
    float xa[64];
    #pragma unroll
    for (int j = 0; j < 64; j++) xa[j] = 0.f;
    #pragma unroll
    for (int h = 0; h < NH; h++) {
        const float4* krow = (const float4*)&kv[lt][h * 64];
        #pragma unroll
        for (int j4 = 0; j4 < 16; j4++) {
            float4 kk = krow[j4];
            xa[j4 * 4 + 0] = fmaf(q[h], kk.x, xa[j4 * 4 + 0]);
            xa[j4 * 4 + 1] = fmaf(q[h], kk.y, xa[j4 * 4 + 1]);
            xa[j4 * 4 + 2] = fmaf(q[h], kk.z, xa[j4 * 4 + 2]);
            xa[j4 * 4 + 3] = fmaf(q[h], kk.w, xa[j4 * 4 + 3]);
        }
    }

    // row max
    float mx = xa[0];
    #pragma unroll
    for (int j = 1; j < 64; j++) mx = fmaxf(mx, xa[j]);

    float tau_lo = mx - 1.f;
    float dm     = 1.f - exp2f(-6.f * am1);   // 1 - (1/64)^am1
    float tau_m  = tau_lo;

    if (fast) {
        float f_lo = -1.f;
        #pragma unroll
        for (int j = 0; j < 64; j++) {
            float t = fmaxf(xa[j] - tau_lo, 0.f);
            f_lo = fmaf(t, t, f_lo);
        }
        for (int it = 0; it < NITER; it++) {
            dm *= 0.5f;
            tau_m = tau_lo + dm;
            float fm = -1.f;
            #pragma unroll
            for (int j = 0; j < 64; j++) {
                float t = fmaxf(xa[j] - tau_m, 0.f);
                fm = fmaf(t, t, fm);
            }
            if (fm * f_lo >= 0.f) tau_lo = tau_m;
        }
        // p and sum
        float s = 0.f;
        #pragma unroll
        for (int j = 0; j < 64; j++) {
            float t = fmaxf(xa[j] - tau_m, 0.f);
            float p = t * t;
            xa[j] = p;
            s += p;
        }
        float rs = 1.f / s;
        #pragma unroll
        for (int j = 0; j < 64; j++) xa[j] *= rs;
    } else {
        // general-alpha fallback: p(z) = clamp(z,0)^(1/(alpha-1))
        float f_lo = -1.f;
        #pragma unroll
        for (int j = 0; j < 64; j++) {
            float z = xa[j] - tau_lo;
            f_lo += (z > 0.f) ? powf(fmaxf(z, 1e-30f), inv) : 0.f;
        }
        for (int it = 0; it < NITER; it++) {
            dm *= 0.5f;
            tau_m = tau_lo + dm;
            float fm = -1.f;
            #pragma unroll
            for (int j = 0; j < 64; j++) {
                float z = xa[j] - tau_m;
                fm += (z > 0.f) ? powf(fmaxf(z, 1e-30f), inv) : 0.f;
            }
            if (fm * f_lo >= 0.f) tau_lo = tau_m;
        }
        float s = 0.f;
        #pragma unroll
        for (int j = 0; j < 64; j++) {
            float z = xa[j] - tau_m;
            float p = (z > 0.f) ? powf(fmaxf(z, 1e-30f), inv) : 0.f;
            xa[j] = p;
            s += p;
        }
        float rs = 1.f / s;
        #pragma unroll
        for (int j = 0; j < 64; j++) xa[j] *= rs;
    }

    // res[h][i] = sum_j att[i][j] * v[h][j]; coalesced scalar stores per h
    #pragma unroll
    for (int h = 0; h < NH; h++) {
        const float4* vrow = (const float4*)&kv[lt][512 + h * 64];
        float acc = 0.f;
        #pragma unroll
        for (int j4 = 0; j4 < 16; j4++) {
            float4 vv = vrow[j4];
            acc = fmaf(xa[j4 * 4 + 0], vv.x, acc);
            acc = fmaf(xa[j4 * 4 + 1], vv.y, acc);
            acc = fmaf(xa[j4 * 4 + 2], vv.z, acc);
            acc = fmaf(xa[j4 * 4 + 3], vv.w, acc);
        }
        g_res[(size_t)token * HE + h * 64 + i] = acc;
    }
}

// ---------------------------------------------------------------------------
// K3: output projection.  out[n,o] = sum_k res[n,k]*Wu[o,k] + bu[o]
// Tile: M=128, N=64, K=512 in 8 chunks of 64.
// ---------------------------------------------------------------------------
__global__ __launch_bounds__(256) void k_out(
    const float* __restrict__ Wu, const float* __restrict__ bu,
    float* __restrict__ out)
{
    __shared__ float aT[64][128];  // aT[k][m]
    __shared__ float bT[64][64];   // bT[k][o]
    const int tid = threadIdx.x;
    const int bm  = blockIdx.x;    // 0..127
    const int m0  = (tid >> 4) * 8;
    const int c0  = (tid & 15) * 4;

    float acc[8][4];
    #pragma unroll
    for (int r = 0; r < 8; r++)
        #pragma unroll
        for (int c = 0; c < 4; c++) acc[r][c] = 0.f;

    for (int kc = 0; kc < 8; kc++) {
        __syncthreads();
        // A chunk: 128 rows x 64 k
        {
            int f = tid;
            #pragma unroll
            for (int rep = 0; rep < 8; rep++, f += 256) {
                int m  = f >> 4;
                int c4 = f & 15;
                float4 v = *(const float4*)(g_res + (size_t)(bm * 128 + m) * HE + kc * 64 + c4 * 4);
                aT[c4 * 4 + 0][m] = v.x;
                aT[c4 * 4 + 1][m] = v.y;
                aT[c4 * 4 + 2][m] = v.z;
                aT[c4 * 4 + 3][m] = v.w;
            }
        }
        // B chunk: 64 o x 64 k
        {
            int f = tid;
            #pragma unroll
            for (int rep = 0; rep < 4; rep++, f += 256) {
                int o  = f >> 4;
                int c4 = f & 15;
                float4 v = *(const float4*)(Wu + (size_t)o * HE + kc * 64 + c4 * 4);
                bT[c4 * 4 + 0][o] = v.x;
                bT[c4 * 4 + 1][o] = v.y;
                bT[c4 * 4 + 2][o] = v.z;
                bT[c4 * 4 + 3][o] = v.w;
            }
        }
        __syncthreads();

        #pragma unroll 8
        for (int k = 0; k < 64; k++) {
            float4 a4a = *(const float4*)&aT[k][m0];
            float4 a4b = *(const float4*)&aT[k][m0 + 4];
            float4 b4  = *(const float4*)&bT[k][c0];
            float a[8] = {a4a.x, a4a.y, a4a.z, a4a.w, a4b.x, a4b.y, a4b.z, a4b.w};
            float b[4] = {b4.x, b4.y, b4.z, b4.w};
            #pragma unroll
            for (int r = 0; r < 8; r++)
                #pragma unroll
                for (int c = 0; c < 4; c++)
                    acc[r][c] = fmaf(a[r], b[c], acc[r][c]);
        }
    }

    float4 bb = *(const float4*)(bu + c0);
    #pragma unroll
    for (int r = 0; r < 8; r++) {
        float4 o4 = make_float4(acc[r][0] + bb.x, acc[r][1] + bb.y,
                                acc[r][2] + bb.z, acc[r][3] + bb.w);
        *(float4*)(out + (size_t)(bm * 128 + m0 + r) * 64 + c0) = o4;
    }
}

// ---------------------------------------------------------------------------
extern "C" void kernel_launch(void* const* d_in, const int* in_sizes, int n_in,
                              void* d_out, int out_size)
{
    const float* x     = (const float*)d_in[0];
    const float* alpha = (const float*)d_in[1];
    const float* Wk    = (const float*)d_in[2];
    const float* bk    = (const float*)d_in[3];
    const float* Wq    = (const float*)d_in[4];
    const float* bq    = (const float*)d_in[5];
    const float* Wv    = (const float*)d_in[6];
    const float* bv    = (const float*)d_in[7];
    const float* Wu    = (const float*)d_in[8];
    const float* bu    = (const float*)d_in[9];
    float* out = (float*)d_out;

    k_qkv<<<dim3(256, 12), 256>>>(x, Wq, bq, Wk, bk, Wv, bv, alpha);
    k_attn<<<NTOK / 4, 256>>>(alpha);
    k_out<<<NTOK / 128, 256>>>(Wu, bu, out);
}

// round 2
// speedup vs baseline: 1.4336x; 1.4336x over previous
#include <cuda_runtime.h>
#include <math.h>

#define NTOK   16384
#define EDIM   64
#define NH     8
#define HE     512
#define QKVDIM 1536
#define NITER  22

// Scratch (static device memory — allocation-free)
__device__ float g_qkv[NTOK * QKVDIM];   // per token: q[0:512) (pre-scaled), k[512:1024), v[1024:1536)
__device__ float g_res[NTOK * HE];       // per token: res[h*64+i]

// ---------------------------------------------------------------------------
// K1: fused QKV projection.  y[n,o] = sum_k x[n,k]*W[o,k] + b[o]
// Tile: M=128 tokens x N=128 outputs, K=64 in 2 chunks of 32. 8x8 per thread.
// smem rows padded to 132 floats: transpose-store stride 132 -> bank stride 4
// (2-way worst case) instead of the old stride-64 16-way conflict.
// ---------------------------------------------------------------------------
__global__ __launch_bounds__(256, 2) void k_qkv(
    const float* __restrict__ x,
    const float* __restrict__ Wq, const float* __restrict__ bq,
    const float* __restrict__ Wk, const float* __restrict__ bk,
    const float* __restrict__ Wv, const float* __restrict__ bv,
    const float* __restrict__ alpha_p)
{
    __shared__ float aT[32][132];   // aT[k][m]
    __shared__ float bT[32][132];   // bT[k][o]
    const int tid   = threadIdx.x;
    const int bm    = blockIdx.x;           // 0..127 (token tiles of 128)
    const int oBase = blockIdx.y * 128;     // 0..1408 step 128

    // select weight matrix for this N-tile (no straddle: 512 % 128 == 0)
    const float* W; const float* bias;
    if (oBase < 512)       { W = Wq; bias = bq; }
    else if (oBase < 1024) { W = Wk; bias = bk; }
    else                   { W = Wv; bias = bv; }
    const int wBase = oBase & 511;

    const int r0 = (tid >> 4) * 8;   // 0..120
    const int c0 = (tid & 15) * 8;   // 0..120

    float acc[8][8];
    #pragma unroll
    for (int r = 0; r < 8; r++)
        #pragma unroll
        for (int c = 0; c < 8; c++) acc[r][c] = 0.f;

    #pragma unroll
    for (int kc = 0; kc < 2; kc++) {
        __syncthreads();
        // A chunk: 128 rows x 32 k  (1024 float4, 4 per thread)
        {
            int f = tid;
            #pragma unroll
            for (int rep = 0; rep < 4; rep++, f += 256) {
                int row = f >> 3;       // 0..127
                int c4  = f & 7;        // k-group
                float4 v = *(const float4*)(x + (size_t)(bm * 128 + row) * 64 + kc * 32 + c4 * 4);
                aT[c4 * 4 + 0][row] = v.x;
                aT[c4 * 4 + 1][row] = v.y;
                aT[c4 * 4 + 2][row] = v.z;
                aT[c4 * 4 + 3][row] = v.w;
            }
        }
        // B chunk: 128 outputs x 32 k
        {
            int f = tid;
            #pragma unroll
            for (int rep = 0; rep < 4; rep++, f += 256) {
                int o  = f >> 3;
                int c4 = f & 7;
                float4 v = *(const float4*)(W + (size_t)(wBase + o) * 64 + kc * 32 + c4 * 4);
                bT[c4 * 4 + 0][o] = v.x;
                bT[c4 * 4 + 1][o] = v.y;
                bT[c4 * 4 + 2][o] = v.z;
                bT[c4 * 4 + 3][o] = v.w;
            }
        }
        __syncthreads();

        #pragma unroll 8
        for (int k = 0; k < 32; k++) {
            float4 a0 = *(const float4*)&aT[k][r0];
            float4 a1 = *(const float4*)&aT[k][r0 + 4];
            float4 b0 = *(const float4*)&bT[k][c0];
            float4 b1 = *(const float4*)&bT[k][c0 + 4];
            float a[8] = {a0.x, a0.y, a0.z, a0.w, a1.x, a1.y, a1.z, a1.w};
            float b[8] = {b0.x, b0.y, b0.z, b0.w, b1.x, b1.y, b1.z, b1.w};
            #pragma unroll
            for (int r = 0; r < 8; r++)
                #pragma unroll
                for (int c = 0; c < 8; c++)
                    acc[r][c] = fmaf(a[r], b[c], acc[r][c]);
        }
    }

    const float am1   = alpha_p[0] - 1.f;
    const float scale = (oBase < 512) ? am1 * 0.125f : 1.f;   // 1/sqrt(64)=0.125

    float bb[8];
    #pragma unroll
    for (int c = 0; c < 8; c++) bb[c] = bias[wBase + c0 + c];

    #pragma unroll
    for (int r = 0; r < 8; r++) {
        float o[8];
        #pragma unroll
        for (int c = 0; c < 8; c++) o[c] = (acc[r][c] + bb[c]) * scale;
        float* dst = g_qkv + (size_t)(bm * 128 + r0 + r) * QKVDIM + oBase + c0;
        *(float4*)(dst)     = make_float4(o[0], o[1], o[2], o[3]);
        *(float4*)(dst + 4) = make_float4(o[4], o[5], o[6], o[7]);
    }
}

// ---------------------------------------------------------------------------
// K2: per-token attention scores + entmax bisection + att@V^T.
// 4 tokens per CTA, 64 threads per token, one score row per thread in regs.
// ---------------------------------------------------------------------------
__global__ __launch_bounds__(256) void k_attn(const float* __restrict__ alpha_p)
{
    __shared__ float kv[4][1024];   // per local token: k[0:512), v[512:1024)
    const int tid   = threadIdx.x;
    const int tok0  = blockIdx.x * 4;
    const int lt    = tid >> 6;       // local token
    const int i     = tid & 63;       // score row
    const int token = tok0 + lt;

    // cooperative load of k,v for 4 tokens (1024 float4)
    {
        int f = tid;
        #pragma unroll
        for (int rep = 0; rep < 4; rep++, f += 256) {
            int t    = f >> 8;
            int idx4 = f & 255;
            float4 v = *(const float4*)(g_qkv + (size_t)(tok0 + t) * QKVDIM + 512 + idx4 * 4);
            *(float4*)(&kv[t][idx4 * 4]) = v;
        }
    }
    // per-thread q column (pre-scaled by am1/sqrt(e) in K1)
    float q[NH];
    #pragma unroll
    for (int h = 0; h < NH; h++)
        q[h] = g_qkv[(size_t)token * QKVDIM + h * 64 + i];
    __syncthreads();

    const float am1 = alpha_p[0] - 1.f;
    const float inv = 1.f / am1;
    const bool fast = fabsf(inv - 2.f) < 1e-4f;   // alpha == 1.5 -> p(z)=z^2

    // Xa row: xa[j] = sum_h q[h] * k[h][j]
    float xa[64];
    #pragma unroll
    for (int j = 0; j < 64; j++) xa[j] = 0.f;
    #pragma unroll
    for (int h = 0; h < NH; h++) {
        const float4* krow = (const float4*)&kv[lt][h * 64];
        #pragma unroll
        for (int j4 = 0; j4 < 16; j4++) {
            float4 kk = krow[j4];
            xa[j4 * 4 + 0] = fmaf(q[h], kk.x, xa[j4 * 4 + 0]);
            xa[j4 * 4 + 1] = fmaf(q[h], kk.y, xa[j4 * 4 + 1]);
            xa[j4 * 4 + 2] = fmaf(q[h], kk.z, xa[j4 * 4 + 2]);
            xa[j4 * 4 + 3] = fmaf(q[h], kk.w, xa[j4 * 4 + 3]);
        }
    }

    // row max
    float mx = xa[0];
    #pragma unroll
    for (int j = 1; j < 64; j++) mx = fmaxf(mx, xa[j]);

    float tau_lo = mx - 1.f;
    float dm     = 1.f - exp2f(-6.f * am1);   // 1 - (1/64)^am1
    float tau_m  = tau_lo;

    if (fast) {
        float a0 = -1.f, a1 = 0.f, a2 = 0.f, a3 = 0.f;
        #pragma unroll
        for (int j = 0; j < 16; j++) {
            float t0 = fmaxf(xa[j]      - tau_lo, 0.f);
            float t1 = fmaxf(xa[j + 16] - tau_lo, 0.f);
            float t2 = fmaxf(xa[j + 32] - tau_lo, 0.f);
            float t3 = fmaxf(xa[j + 48] - tau_lo, 0.f);
            a0 = fmaf(t0, t0, a0); a1 = fmaf(t1, t1, a1);
            a2 = fmaf(t2, t2, a2); a3 = fmaf(t3, t3, a3);
        }
        const float f_lo = (a0 + a1) + (a2 + a3);

        for (int it = 0; it < NITER; it++) {
            dm *= 0.5f;
            tau_m = tau_lo + dm;
            float m0 = -1.f, m1 = 0.f, m2 = 0.f, m3 = 0.f;
            #pragma unroll
            for (int j = 0; j < 16; j++) {
                float t0 = fmaxf(xa[j]      - tau_m, 0.f);
                float t1 = fmaxf(xa[j + 16] - tau_m, 0.f);
                float t2 = fmaxf(xa[j + 32] - tau_m, 0.f);
                float t3 = fmaxf(xa[j + 48] - tau_m, 0.f);
                m0 = fmaf(t0, t0, m0); m1 = fmaf(t1, t1, m1);
                m2 = fmaf(t2, t2, m2); m3 = fmaf(t3, t3, m3);
            }
            float fm = (m0 + m1) + (m2 + m3);
            if (fm * f_lo >= 0.f) tau_lo = tau_m;
        }
        // p and sum
        float s0 = 0.f, s1 = 0.f, s2 = 0.f, s3 = 0.f;
        #pragma unroll
        for (int j = 0; j < 16; j++) {
            float t0 = fmaxf(xa[j]      - tau_m, 0.f);
            float t1 = fmaxf(xa[j + 16] - tau_m, 0.f);
            float t2 = fmaxf(xa[j + 32] - tau_m, 0.f);
            float t3 = fmaxf(xa[j + 48] - tau_m, 0.f);
            xa[j]      = t0 * t0; xa[j + 16] = t1 * t1;
            xa[j + 32] = t2 * t2; xa[j + 48] = t3 * t3;
            s0 = fmaf(t0, t0, s0); s1 = fmaf(t1, t1, s1);
            s2 = fmaf(t2, t2, s2); s3 = fmaf(t3, t3, s3);
        }
        float rs = 1.f / ((s0 + s1) + (s2 + s3));
        #pragma unroll
        for (int j = 0; j < 64; j++) xa[j] *= rs;
    } else {
        // general-alpha fallback: p(z) = clamp(z,0)^(1/(alpha-1))
        float f_lo = -1.f;
        #pragma unroll
        for (int j = 0; j < 64; j++) {
            float z = xa[j] - tau_lo;
            f_lo += (z > 0.f) ? powf(fmaxf(z, 1e-30f), inv) : 0.f;
        }
        for (int it = 0; it < NITER; it++) {
            dm *= 0.5f;
            tau_m = tau_lo + dm;
            float fm = -1.f;
            #pragma unroll
            for (int j = 0; j < 64; j++) {
                float z = xa[j] - tau_m;
                fm += (z > 0.f) ? powf(fmaxf(z, 1e-30f), inv) : 0.f;
            }
            if (fm * f_lo >= 0.f) tau_lo = tau_m;
        }
        float s = 0.f;
        #pragma unroll
        for (int j = 0; j < 64; j++) {
            float z = xa[j] - tau_m;
            float p = (z > 0.f) ? powf(fmaxf(z, 1e-30f), inv) : 0.f;
            xa[j] = p;
            s += p;
        }
        float rs = 1.f / s;
        #pragma unroll
        for (int j = 0; j < 64; j++) xa[j] *= rs;
    }

    // res[h][i] = sum_j att[i][j] * v[h][j]; coalesced scalar stores per h
    #pragma unroll
    for (int h = 0; h < NH; h++) {
        const float4* vrow = (const float4*)&kv[lt][512 + h * 64];
        float c0 = 0.f, c1 = 0.f;
        #pragma unroll
        for (int j4 = 0; j4 < 8; j4++) {
            float4 v0 = vrow[j4];
            float4 v1 = vrow[j4 + 8];
            c0 = fmaf(xa[j4 * 4 + 0], v0.x, c0);
            c0 = fmaf(xa[j4 * 4 + 1], v0.y, c0);
            c0 = fmaf(xa[j4 * 4 + 2], v0.z, c0);
            c0 = fmaf(xa[j4 * 4 + 3], v0.w, c0);
            c1 = fmaf(xa[32 + j4 * 4 + 0], v1.x, c1);
            c1 = fmaf(xa[32 + j4 * 4 + 1], v1.y, c1);
            c1 = fmaf(xa[32 + j4 * 4 + 2], v1.z, c1);
            c1 = fmaf(xa[32 + j4 * 4 + 3], v1.w, c1);
        }
        g_res[(size_t)token * HE + h * 64 + i] = c0 + c1;
    }
}

// ---------------------------------------------------------------------------
// K3: output projection.  out[n,o] = sum_k res[n,k]*Wu[o,k] + bu[o]
// Tile: M=128, N=64, K=512 in 16 chunks of 32.  8x4 per thread.
// Padded smem rows kill the transpose-store conflicts.
// ---------------------------------------------------------------------------
__global__ __launch_bounds__(256) void k_out(
    const float* __restrict__ Wu, const float* __restrict__ bu,
    float* __restrict__ out)
{
    __shared__ float aT[32][132];  // aT[k][m]
    __shared__ float bT[32][68];   // bT[k][o]
    const int tid = threadIdx.x;
    const int bm  = blockIdx.x;    // 0..127
    const int m0  = (tid >> 4) * 8;
    const int c0  = (tid & 15) * 4;

    float acc[8][4];
    #pragma unroll
    for (int r = 0; r < 8; r++)
        #pragma unroll
        for (int c = 0; c < 4; c++) acc[r][c] = 0.f;

    for (int kc = 0; kc < 16; kc++) {
        __syncthreads();
        // A chunk: 128 rows x 32 k (1024 float4, 4 per thread)
        {
            int f = tid;
            #pragma unroll
            for (int rep = 0; rep < 4; rep++, f += 256) {
                int m  = f >> 3;
                int c4 = f & 7;
                float4 v = *(const float4*)(g_res + (size_t)(bm * 128 + m) * HE + kc * 32 + c4 * 4);
                aT[c4 * 4 + 0][m] = v.x;
                aT[c4 * 4 + 1][m] = v.y;
                aT[c4 * 4 + 2][m] = v.z;
                aT[c4 * 4 + 3][m] = v.w;
            }
        }
        // B chunk: 64 o x 32 k (512 float4, 2 per thread)
        {
            int f = tid;
            #pragma unroll
            for (int rep = 0; rep < 2; rep++, f += 256) {
                int o  = f >> 3;
                int c4 = f & 7;
                float4 v = *(const float4*)(Wu + (size_t)o * HE + kc * 32 + c4 * 4);
                bT[c4 * 4 + 0][o] = v.x;
                bT[c4 * 4 + 1][o] = v.y;
                bT[c4 * 4 + 2][o] = v.z;
                bT[c4 * 4 + 3][o] = v.w;
            }
        }
        __syncthreads();

        #pragma unroll 8
        for (int k = 0; k < 32; k++) {
            float4 a4a = *(const float4*)&aT[k][m0];
            float4 a4b = *(const float4*)&aT[k][m0 + 4];
            float4 b4  = *(const float4*)&bT[k][c0];
            float a[8] = {a4a.x, a4a.y, a4a.z, a4a.w, a4b.x, a4b.y, a4b.z, a4b.w};
            float b[4] = {b4.x, b4.y, b4.z, b4.w};
            #pragma unroll
            for (int r = 0; r < 8; r++)
                #pragma unroll
                for (int c = 0; c < 4; c++)
                    acc[r][c] = fmaf(a[r], b[c], acc[r][c]);
        }
    }

    float4 bb = *(const float4*)(bu + c0);
    #pragma unroll
    for (int r = 0; r < 8; r++) {
        float4 o4 = make_float4(acc[r][0] + bb.x, acc[r][1] + bb.y,
                                acc[r][2] + bb.z, acc[r][3] + bb.w);
        *(float4*)(out + (size_t)(bm * 128 + m0 + r) * 64 + c0) = o4;
    }
}

// ---------------------------------------------------------------------------
extern "C" void kernel_launch(void* const* d_in, const int* in_sizes, int n_in,
                              void* d_out, int out_size)
{
    const float* x     = (const float*)d_in[0];
    const float* alpha = (const float*)d_in[1];
    const float* Wk    = (const float*)d_in[2];
    const float* bk    = (const float*)d_in[3];
    const float* Wq    = (const float*)d_in[4];
    const float* bq    = (const float*)d_in[5];
    const float* Wv    = (const float*)d_in[6];
    const float* bv    = (const float*)d_in[7];
    const float* Wu    = (const float*)d_in[8];
    const float* bu    = (const float*)d_in[9];
    float* out = (float*)d_out;

    k_qkv<<<dim3(128, 12), 256>>>(x, Wq, bq, Wk, bk, Wv, bv, alpha);
    k_attn<<<NTOK / 4, 256>>>(alpha);
    k_out<<<NTOK / 128, 256>>>(Wu, bu, out);
}

// round 3
// speedup vs baseline: 1.6761x; 1.1691x over previous
#include <cuda_runtime.h>
#include <math.h>

#define NTOK   16384
#define EDIM   64
#define NH     8
#define HE     512
#define QKVDIM 1536
#define NITER  16

typedef unsigned long long ull;

// Scratch (static device memory — allocation-free)
__device__ float g_qkv[NTOK * QKVDIM];   // per token: q[0:512) (pre-scaled), k[512:1024), v[1024:1536)
__device__ float g_res[NTOK * HE];       // per token: res[h*64+i]

// ---------------- f32x2 packed-math helpers (Blackwell FFMA2 path) ----------
__device__ __forceinline__ ull pack2(float lo, float hi) {
    ull r; asm("mov.b64 %0, {%1, %2};" : "=l"(r) : "f"(lo), "f"(hi)); return r;
}
__device__ __forceinline__ ull dup2(float v) { return pack2(v, v); }
__device__ __forceinline__ float lo2(ull v) {
    float f; asm("{ .reg .b32 hi; mov.b64 {%0, hi}, %1; }" : "=f"(f) : "l"(v)); return f;
}
__device__ __forceinline__ float hi2(ull v) {
    float f; asm("{ .reg .b32 lo; mov.b64 {lo, %0}, %1; }" : "=f"(f) : "l"(v)); return f;
}
__device__ __forceinline__ void ffma2(ull& d, ull a, ull b) {
    asm("fma.rn.f32x2 %0, %1, %2, %0;" : "+l"(d) : "l"(a), "l"(b));
}
__device__ __forceinline__ ull add2(ull a, ull b) {
    ull r; asm("add.rn.f32x2 %0, %1, %2;" : "=l"(r) : "l"(a), "l"(b)); return r;
}
__device__ __forceinline__ ull mul2(ull a, ull b) {
    ull r; asm("mul.rn.f32x2 %0, %1, %2;" : "=l"(r) : "l"(a), "l"(b)); return r;
}
__device__ __forceinline__ float hsum2(ull v) { return lo2(v) + hi2(v); }
// relu(x + nt) on both packed halves: 1 add.f32x2 + 2 scalar max on the halves
__device__ __forceinline__ ull relu2_add(ull x2, ull nt2) {
    ull r;
    asm("{\n\t"
        ".reg .f32 lo, hi;\n\t"
        "add.rn.f32x2 %0, %1, %2;\n\t"
        "mov.b64 {lo, hi}, %0;\n\t"
        "max.f32 lo, lo, 0f00000000;\n\t"
        "max.f32 hi, hi, 0f00000000;\n\t"
        "mov.b64 %0, {lo, hi};\n\t"
        "}" : "=l"(r) : "l"(x2), "l"(nt2));
    return r;
}

// ---------------------------------------------------------------------------
// K1: fused QKV projection.  y[n,o] = sum_k x[n,k]*W[o,k] + b[o]
// Tile: M=128 x N=128, K=64 in 2 chunks of 32. 8 rows x 4 col-pairs (FFMA2).
// ---------------------------------------------------------------------------
__global__ __launch_bounds__(256, 2) void k_qkv(
    const float* __restrict__ x,
    const float* __restrict__ Wq, const float* __restrict__ bq,
    const float* __restrict__ Wk, const float* __restrict__ bk,
    const float* __restrict__ Wv, const float* __restrict__ bv,
    const float* __restrict__ alpha_p)
{
    __shared__ float aT[32][132];   // aT[k][m]
    __shared__ float bT[32][132];   // bT[k][o]
    const int tid   = threadIdx.x;
    const int bm    = blockIdx.x;           // 0..127
    const int oBase = blockIdx.y * 128;     // 0..1408 step 128

    const float* W; const float* bias;
    if (oBase < 512)       { W = Wq; bias = bq; }
    else if (oBase < 1024) { W = Wk; bias = bk; }
    else                   { W = Wv; bias = bv; }
    const int wBase = oBase & 511;

    const int r0 = (tid >> 4) * 8;   // 0..120
    const int c0 = (tid & 15) * 8;   // 0..120

    ull acc2[8][4];                  // [row][col-pair]
    #pragma unroll
    for (int r = 0; r < 8; r++)
        #pragma unroll
        for (int c = 0; c < 4; c++) acc2[r][c] = 0ULL;

    #pragma unroll
    for (int kc = 0; kc < 2; kc++) {
        __syncthreads();
        {   // A chunk: 128 rows x 32 k
            int f = tid;
            #pragma unroll
            for (int rep = 0; rep < 4; rep++, f += 256) {
                int row = f >> 3;
                int c4  = f & 7;
                float4 v = *(const float4*)(x + (size_t)(bm * 128 + row) * 64 + kc * 32 + c4 * 4);
                aT[c4 * 4 + 0][row] = v.x;
                aT[c4 * 4 + 1][row] = v.y;
                aT[c4 * 4 + 2][row] = v.z;
                aT[c4 * 4 + 3][row] = v.w;
            }
        }
        {   // B chunk: 128 outputs x 32 k
            int f = tid;
            #pragma unroll
            for (int rep = 0; rep < 4; rep++, f += 256) {
                int o  = f >> 3;
                int c4 = f & 7;
                float4 v = *(const float4*)(W + (size_t)(wBase + o) * 64 + kc * 32 + c4 * 4);
                bT[c4 * 4 + 0][o] = v.x;
                bT[c4 * 4 + 1][o] = v.y;
                bT[c4 * 4 + 2][o] = v.z;
                bT[c4 * 4 + 3][o] = v.w;
            }
        }
        __syncthreads();

        #pragma unroll 8
        for (int k = 0; k < 32; k++) {
            float4 a0 = *(const float4*)&aT[k][r0];
            float4 a1 = *(const float4*)&aT[k][r0 + 4];
            float4 b0 = *(const float4*)&bT[k][c0];
            float4 b1 = *(const float4*)&bT[k][c0 + 4];
            ull bp[4] = {pack2(b0.x, b0.y), pack2(b0.z, b0.w),
                         pack2(b1.x, b1.y), pack2(b1.z, b1.w)};
            float a[8] = {a0.x, a0.y, a0.z, a0.w, a1.x, a1.y, a1.z, a1.w};
            #pragma unroll
            for (int r = 0; r < 8; r++) {
                ull ad = dup2(a[r]);
                #pragma unroll
                for (int c = 0; c < 4; c++) ffma2(acc2[r][c], ad, bp[c]);
            }
        }
    }

    const float am1   = alpha_p[0] - 1.f;
    const float scale = (oBase < 512) ? am1 * 0.125f : 1.f;
    const ull   sc2   = dup2(scale);

    ull bb2[4];
    #pragma unroll
    for (int c = 0; c < 4; c++)
        bb2[c] = pack2(bias[wBase + c0 + 2 * c], bias[wBase + c0 + 2 * c + 1]);

    #pragma unroll
    for (int r = 0; r < 8; r++) {
        float* dst = g_qkv + (size_t)(bm * 128 + r0 + r) * QKVDIM + oBase + c0;
        #pragma unroll
        for (int c = 0; c < 4; c++) {
            ull o2 = mul2(add2(acc2[r][c], bb2[c]), sc2);
            *(ull*)(dst + 2 * c) = o2;   // STG.64 of two packed floats
        }
    }
}

// ---------------------------------------------------------------------------
// K2: per-token attention scores + entmax bisection + att@V^T (packed f32x2).
// 4 tokens per CTA, 64 threads per token, one score row per thread in regs.
// ---------------------------------------------------------------------------
__global__ __launch_bounds__(256) void k_attn(const float* __restrict__ alpha_p)
{
    __shared__ float kv[4][1024];   // per local token: k[0:512), v[512:1024)
    const int tid   = threadIdx.x;
    const int tok0  = blockIdx.x * 4;
    const int lt    = tid >> 6;
    const int i     = tid & 63;
    const int token = tok0 + lt;

    {   // cooperative load of k,v for 4 tokens
        int f = tid;
        #pragma unroll
        for (int rep = 0; rep < 4; rep++, f += 256) {
            int t    = f >> 8;
            int idx4 = f & 255;
            float4 v = *(const float4*)(g_qkv + (size_t)(tok0 + t) * QKVDIM + 512 + idx4 * 4);
            *(float4*)(&kv[t][idx4 * 4]) = v;
        }
    }
    float q[NH];
    #pragma unroll
    for (int h = 0; h < NH; h++)
        q[h] = g_qkv[(size_t)token * QKVDIM + h * 64 + i];
    __syncthreads();

    const float am1 = alpha_p[0] - 1.f;
    const float inv = 1.f / am1;
    const bool fast = fabsf(inv - 2.f) < 1e-4f;

    // Xa row as 32 packed pairs
    ull xa2[32];
    #pragma unroll
    for (int p = 0; p < 32; p++) xa2[p] = 0ULL;
    #pragma unroll
    for (int h = 0; h < NH; h++) {
        ull q2 = dup2(q[h]);
        const float4* krow = (const float4*)&kv[lt][h * 64];
        #pragma unroll
        for (int j4 = 0; j4 < 16; j4++) {
            float4 kk = krow[j4];
            ffma2(xa2[j4 * 2 + 0], q2, pack2(kk.x, kk.y));
            ffma2(xa2[j4 * 2 + 1], q2, pack2(kk.z, kk.w));
        }
    }

    // row max
    float mx = -3.4e38f;
    #pragma unroll
    for (int p = 0; p < 32; p++)
        mx = fmaxf(mx, fmaxf(lo2(xa2[p]), hi2(xa2[p])));

    float tau_lo = mx - 1.f;
    float dm     = 1.f - exp2f(-6.f * am1);   // 1 - (1/64)^am1
    float tau_m  = tau_lo;

    if (fast) {
        float f_lo;
        {
            ull nt = dup2(-tau_lo);
            ull a0 = pack2(-1.f, 0.f), a1 = 0ULL, a2 = 0ULL, a3 = 0ULL;
            #pragma unroll
            for (int j = 0; j < 8; j++) {
                ull t;
                t = relu2_add(xa2[j],      nt); ffma2(a0, t, t);
                t = relu2_add(xa2[j +  8], nt); ffma2(a1, t, t);
                t = relu2_add(xa2[j + 16], nt); ffma2(a2, t, t);
                t = relu2_add(xa2[j + 24], nt); ffma2(a3, t, t);
            }
            f_lo = hsum2(add2(add2(a0, a1), add2(a2, a3)));
        }
        for (int it = 0; it < NITER; it++) {
            dm *= 0.5f;
            tau_m = tau_lo + dm;
            ull nt = dup2(-tau_m);
            ull a0 = pack2(-1.f, 0.f), a1 = 0ULL, a2 = 0ULL, a3 = 0ULL;
            #pragma unroll
            for (int j = 0; j < 8; j++) {
                ull t;
                t = relu2_add(xa2[j],      nt); ffma2(a0, t, t);
                t = relu2_add(xa2[j +  8], nt); ffma2(a1, t, t);
                t = relu2_add(xa2[j + 16], nt); ffma2(a2, t, t);
                t = relu2_add(xa2[j + 24], nt); ffma2(a3, t, t);
            }
            float fm = hsum2(add2(add2(a0, a1), add2(a2, a3)));
            if (fm * f_lo >= 0.f) tau_lo = tau_m;
        }
        // p and normalize
        {
            ull nt = dup2(-tau_m);
            ull s0 = 0ULL, s1 = 0ULL;
            #pragma unroll
            for (int p = 0; p < 16; p++) {
                ull t0 = relu2_add(xa2[p],      nt);
                ull t1 = relu2_add(xa2[p + 16], nt);
                ull p0 = mul2(t0, t0);
                ull p1 = mul2(t1, t1);
                xa2[p]      = p0;
                xa2[p + 16] = p1;
                ffma2(s0, t0, t0);
                ffma2(s1, t1, t1);
            }
            float rs = 1.f / hsum2(add2(s0, s1));
            ull rs2 = dup2(rs);
            #pragma unroll
            for (int p = 0; p < 32; p++) xa2[p] = mul2(xa2[p], rs2);
        }
    } else {
        // general-alpha fallback: p(z) = clamp(z,0)^(1/(alpha-1)) (scalar)
        float xs[64];
        #pragma unroll
        for (int p = 0; p < 32; p++) { xs[2 * p] = lo2(xa2[p]); xs[2 * p + 1] = hi2(xa2[p]); }
        float f_lo = -1.f;
        #pragma unroll
        for (int j = 0; j < 64; j++) {
            float z = xs[j] - tau_lo;
            f_lo += (z > 0.f) ? powf(fmaxf(z, 1e-30f), inv) : 0.f;
        }
        for (int it = 0; it < NITER; it++) {
            dm *= 0.5f;
            tau_m = tau_lo + dm;
            float fm = -1.f;
            #pragma unroll
            for (int j = 0; j < 64; j++) {
                float z = xs[j] - tau_m;
                fm += (z > 0.f) ? powf(fmaxf(z, 1e-30f), inv) : 0.f;
            }
            if (fm * f_lo >= 0.f) tau_lo = tau_m;
        }
        float s = 0.f;
        #pragma unroll
        for (int j = 0; j < 64; j++) {
            float z = xs[j] - tau_m;
            float p = (z > 0.f) ? powf(fmaxf(z, 1e-30f), inv) : 0.f;
            xs[j] = p;
            s += p;
        }
        float rs = 1.f / s;
        #pragma unroll
        for (int p = 0; p < 32; p++) xa2[p] = pack2(xs[2 * p] * rs, xs[2 * p + 1] * rs);
    }

    // res[h][i] = sum_j att[i][j] * v[h][j]
    #pragma unroll
    for (int h = 0; h < NH; h++) {
        const float4* vrow = (const float4*)&kv[lt][512 + h * 64];
        ull c0 = 0ULL, c1 = 0ULL;
        #pragma unroll
        for (int j4 = 0; j4 < 8; j4++) {
            float4 v0 = vrow[j4];
            float4 v1 = vrow[j4 + 8];
            ffma2(c0, xa2[j4 * 2 + 0],      pack2(v0.x, v0.y));
            ffma2(c0, xa2[j4 * 2 + 1],      pack2(v0.z, v0.w));
            ffma2(c1, xa2[16 + j4 * 2 + 0], pack2(v1.x, v1.y));
            ffma2(c1, xa2[16 + j4 * 2 + 1], pack2(v1.z, v1.w));
        }
        g_res[(size_t)token * HE + h * 64 + i] = hsum2(add2(c0, c1));
    }
}

// ---------------------------------------------------------------------------
// K3: output projection.  out[n,o] = sum_k res[n,k]*Wu[o,k] + bu[o]
// Tile: M=128, N=64, K=512 in 16 chunks of 32. 4 row-pairs x 4 cols (FFMA2).
// ---------------------------------------------------------------------------
__global__ __launch_bounds__(256) void k_out(
    const float* __restrict__ Wu, const float* __restrict__ bu,
    float* __restrict__ out)
{
    __shared__ float aT[32][132];  // aT[k][m]
    __shared__ float bT[32][68];   // bT[k][o]
    const int tid = threadIdx.x;
    const int bm  = blockIdx.x;    // 0..127
    const int m0  = (tid >> 4) * 8;
    const int c0  = (tid & 15) * 4;

    ull acc2[4][4];                // [row-pair][col]
    #pragma unroll
    for (int r = 0; r < 4; r++)
        #pragma unroll
        for (int c = 0; c < 4; c++) acc2[r][c] = 0ULL;

    for (int kc = 0; kc < 16; kc++) {
        __syncthreads();
        {   // A chunk: 128 rows x 32 k
            int f = tid;
            #pragma unroll
            for (int rep = 0; rep < 4; rep++, f += 256) {
                int m  = f >> 3;
                int c4 = f & 7;
                float4 v = *(const float4*)(g_res + (size_t)(bm * 128 + m) * HE + kc * 32 + c4 * 4);
                aT[c4 * 4 + 0][m] = v.x;
                aT[c4 * 4 + 1][m] = v.y;
                aT[c4 * 4 + 2][m] = v.z;
                aT[c4 * 4 + 3][m] = v.w;
            }
        }
        {   // B chunk: 64 o x 32 k
            int f = tid;
            #pragma unroll
            for (int rep = 0; rep < 2; rep++, f += 256) {
                int o  = f >> 3;
                int c4 = f & 7;
                float4 v = *(const float4*)(Wu + (size_t)o * HE + kc * 32 + c4 * 4);
                bT[c4 * 4 + 0][o] = v.x;
                bT[c4 * 4 + 1][o] = v.y;
                bT[c4 * 4 + 2][o] = v.z;
                bT[c4 * 4 + 3][o] = v.w;
            }
        }
        __syncthreads();

        #pragma unroll 8
        for (int k = 0; k < 32; k++) {
            float4 a4a = *(const float4*)&aT[k][m0];
            float4 a4b = *(const float4*)&aT[k][m0 + 4];
            float4 b4  = *(const float4*)&bT[k][c0];
            ull ap[4] = {pack2(a4a.x, a4a.y), pack2(a4a.z, a4a.w),
                         pack2(a4b.x, a4b.y), pack2(a4b.z, a4b.w)};
            float b[4] = {b4.x, b4.y, b4.z, b4.w};
            #pragma unroll
            for (int c = 0; c < 4; c++) {
                ull bd = dup2(b[c]);
                #pragma unroll
                for (int r = 0; r < 4; r++) ffma2(acc2[r][c], ap[r], bd);
            }
        }
    }

    float4 bb = *(const float4*)(bu + c0);
    float bbv[4] = {bb.x, bb.y, bb.z, bb.w};
    #pragma unroll
    for (int rp = 0; rp < 4; rp++) {
        float4 oe, oo;
        float* pe = &oe.x; float* po = &oo.x;
        #pragma unroll
        for (int c = 0; c < 4; c++) {
            pe[c] = lo2(acc2[rp][c]) + bbv[c];
            po[c] = hi2(acc2[rp][c]) + bbv[c];
        }
        *(float4*)(out + (size_t)(bm * 128 + m0 + 2 * rp)     * 64 + c0) = oe;
        *(float4*)(out + (size_t)(bm * 128 + m0 + 2 * rp + 1) * 64 + c0) = oo;
    }
}

// ---------------------------------------------------------------------------
extern "C" void kernel_launch(void* const* d_in, const int* in_sizes, int n_in,
                              void* d_out, int out_size)
{
    const float* x     = (const float*)d_in[0];
    const float* alpha = (const float*)d_in[1];
    const float* Wk    = (const float*)d_in[2];
    const float* bk    = (const float*)d_in[3];
    const float* Wq    = (const float*)d_in[4];
    const float* bq    = (const float*)d_in[5];
    const float* Wv    = (const float*)d_in[6];
    const float* bv    = (const float*)d_in[7];
    const float* Wu    = (const float*)d_in[8];
    const float* bu    = (const float*)d_in[9];
    float* out = (float*)d_out;

    k_qkv<<<dim3(128, 12), 256>>>(x, Wq, bq, Wk, bk, Wv, bv, alpha);
    k_attn<<<NTOK / 4, 256>>>(alpha);
    k_out<<<NTOK / 128, 256>>>(Wu, bu, out);
}